// round 1
// baseline (speedup 1.0000x reference)
#include <cuda_runtime.h>
#include <math.h>

#define S_LEN 2048
#define HID   2048
#define NH    32
#define NKV   8
#define HD    64

// -------- scratch (no allocations allowed) --------
__device__ float g_q   [S_LEN * HID];    // q projection, roped in place
__device__ float g_kr  [S_LEN * 256];    // roped K components (pre-rotation)
__device__ float g_ckv [S_LEN * 256];    // latent
__device__ float g_kc  [S_LEN * 256];    // nope keys (up-proj)
__device__ float g_v   [S_LEN * 512];    // values [s, NKV*HD]
__device__ float g_kf  [S_LEN * 512];    // assembled full keys [s, NKV*HD]
__device__ float g_attn[S_LEN * HID];    // attention output

// ================= generic SGEMM: C[M,N] = A[M,K] * B[N,K]^T =================
// Requires M%128==0, N%128==0, K%8==0.
#define BM 128
#define BN 128
#define BK 8

__global__ __launch_bounds__(256) void sgemm_nt(const float* __restrict__ A,
                                                const float* __restrict__ B,
                                                float* __restrict__ C,
                                                int M, int N, int K) {
    __shared__ float As[BK][BM];
    __shared__ float Bs[BK][BN];

    const int tid = threadIdx.x;
    const int tx  = tid & 15;       // 0..15
    const int ty  = tid >> 4;       // 0..15
    const int m0  = blockIdx.y * BM;
    const int n0  = blockIdx.x * BN;

    const int lrow = tid >> 1;          // 0..127
    const int lcol = (tid & 1) * 4;     // 0 or 4

    float acc[8][8];
    #pragma unroll
    for (int i = 0; i < 8; i++)
        #pragma unroll
        for (int j = 0; j < 8; j++) acc[i][j] = 0.0f;

    for (int k0 = 0; k0 < K; k0 += BK) {
        float4 a4 = *(const float4*)(A + (size_t)(m0 + lrow) * K + k0 + lcol);
        float4 b4 = *(const float4*)(B + (size_t)(n0 + lrow) * K + k0 + lcol);
        As[lcol + 0][lrow] = a4.x; As[lcol + 1][lrow] = a4.y;
        As[lcol + 2][lrow] = a4.z; As[lcol + 3][lrow] = a4.w;
        Bs[lcol + 0][lrow] = b4.x; Bs[lcol + 1][lrow] = b4.y;
        Bs[lcol + 2][lrow] = b4.z; Bs[lcol + 3][lrow] = b4.w;
        __syncthreads();

        #pragma unroll
        for (int kk = 0; kk < BK; kk++) {
            float a[8], b[8];
            *(float4*)(a)     = *(const float4*)&As[kk][ty * 8];
            *(float4*)(a + 4) = *(const float4*)&As[kk][ty * 8 + 4];
            *(float4*)(b)     = *(const float4*)&Bs[kk][tx * 8];
            *(float4*)(b + 4) = *(const float4*)&Bs[kk][tx * 8 + 4];
            #pragma unroll
            for (int i = 0; i < 8; i++)
                #pragma unroll
                for (int j = 0; j < 8; j++)
                    acc[i][j] = fmaf(a[i], b[j], acc[i][j]);
        }
        __syncthreads();
    }

    #pragma unroll
    for (int i = 0; i < 8; i++) {
        float* crow = C + (size_t)(m0 + ty * 8 + i) * N + n0 + tx * 8;
        *(float4*)(crow)     = make_float4(acc[i][0], acc[i][1], acc[i][2], acc[i][3]);
        *(float4*)(crow + 4) = make_float4(acc[i][4], acc[i][5], acc[i][6], acc[i][7]);
    }
}

// ================= RoPE on q (in place) =================
// One block per position s; 1024 threads = 32 heads * 32 pairs.
__global__ void rope_q_kernel() {
    const int s = blockIdx.x;
    const int t = threadIdx.x;
    const int h = t >> 5;       // head
    const int j = t & 31;       // rotation pair index (freq index)
    float inv = powf(10000.0f, -(float)j * (1.0f / 32.0f));
    float sn, cs;
    sincosf((float)s * inv, &sn, &cs);
    float* q = g_q + (size_t)s * HID + h * HD;
    float x = q[j];
    float y = q[j + 32];
    q[j]      = x * cs - y * sn;
    q[j + 32] = y * cs + x * sn;
}

// ================= assemble full key =================
// kf[s][g*64+d]: roped dims (d%32 < 16) from rotated g_kr, nope dims from g_kc.
// Roped column order per head g: dims 0..15 -> cols g*32+0..15, dims 32..47 -> cols g*32+16..31.
// Nope column order per head g: dims 16..31 -> cols g*32+0..15, dims 48..63 -> cols g*32+16..31.
__global__ void make_kf_kernel() {
    const int s = blockIdx.x;
    const int t = threadIdx.x;   // 512
    const int g = t >> 6;
    const int d = t & 63;
    const int j = d & 31;
    float out;
    if (j < 16) {
        const int selfc = g * 32 + ((d < 32) ? j : 16 + j);
        const int partc = g * 32 + ((d < 32) ? 16 + j : j);
        float inv = powf(10000.0f, -(float)j * (1.0f / 32.0f));
        float sn, cs;
        sincosf((float)s * inv, &sn, &cs);
        float x = g_kr[(size_t)s * 256 + selfc];
        float y = g_kr[(size_t)s * 256 + partc];
        out = (d < 32) ? (x * cs - y * sn) : (x * cs + y * sn);
    } else {
        const int cc = g * 32 + ((d < 32) ? (d - 16) : (d - 32));
        out = g_kc[(size_t)s * 256 + cc];
    }
    g_kf[(size_t)s * 512 + g * HD + d] = out;
}

// ================= causal flash attention (fp32) =================
// Block = (q-tile of 64 rows, head). K/V tiles of 32 rows.
__global__ __launch_bounds__(256) void flash_attn_kernel() {
    const int h = blockIdx.y;
    const int i = (int)gridDim.x - 1 - (int)blockIdx.x;   // heavy tiles first
    const int g = h >> 2;                                  // kv head

    __shared__ float Qs[64 * 64];   // Qs[d*64 + r]   (transposed, pre-scaled)
    __shared__ float KV[32 * 64];   // K phase: [d*32 + c]; V phase: [c*64 + v]
    __shared__ float Ps[32 * 64];   // [c*64 + r]  scores then probabilities
    __shared__ float rowM[64], rowL[64], rowA[64];

    const int tid = threadIdx.x;
    const int tx = tid & 15;
    const int ty = tid >> 4;

    for (int idx = tid; idx < 64 * 64; idx += 256) {
        int r = idx >> 6, c = idx & 63;
        Qs[c * 64 + r] = g_q[(size_t)(i * 64 + r) * HID + h * HD + c] * 0.125f;
    }
    if (tid < 64) { rowM[tid] = -INFINITY; rowL[tid] = 0.0f; }

    float o[4][4];
    #pragma unroll
    for (int a = 0; a < 4; a++)
        #pragma unroll
        for (int b = 0; b < 4; b++) o[a][b] = 0.0f;

    __syncthreads();

    const int ntiles = 2 * i + 2;
    for (int j = 0; j < ntiles; j++) {
        // ---- load K tile transposed ----
        for (int idx = tid; idx < 32 * 64; idx += 256) {
            int r = idx >> 6, c = idx & 63;
            KV[c * 32 + r] = g_kf[(size_t)(j * 32 + r) * 512 + g * HD + c];
        }
        __syncthreads();

        // ---- S = Q K^T : rows ty*4.., cols tx*2.. ----
        float sreg[4][2];
        #pragma unroll
        for (int a = 0; a < 4; a++) { sreg[a][0] = 0.0f; sreg[a][1] = 0.0f; }
        #pragma unroll 16
        for (int d = 0; d < 64; d++) {
            float4 a = *(const float4*)&Qs[d * 64 + ty * 4];
            float2 b = *(const float2*)&KV[d * 32 + tx * 2];
            sreg[0][0] = fmaf(a.x, b.x, sreg[0][0]); sreg[0][1] = fmaf(a.x, b.y, sreg[0][1]);
            sreg[1][0] = fmaf(a.y, b.x, sreg[1][0]); sreg[1][1] = fmaf(a.y, b.y, sreg[1][1]);
            sreg[2][0] = fmaf(a.z, b.x, sreg[2][0]); sreg[2][1] = fmaf(a.z, b.y, sreg[2][1]);
            sreg[3][0] = fmaf(a.w, b.x, sreg[3][0]); sreg[3][1] = fmaf(a.w, b.y, sreg[3][1]);
        }
        // ---- causal mask ----
        if (j * 32 + 31 > i * 64) {
            #pragma unroll
            for (int ii = 0; ii < 4; ii++)
                #pragma unroll
                for (int jj = 0; jj < 2; jj++)
                    if (j * 32 + tx * 2 + jj > i * 64 + ty * 4 + ii)
                        sreg[ii][jj] = -1e30f;
        }
        #pragma unroll
        for (int ii = 0; ii < 4; ii++)
            #pragma unroll
            for (int jj = 0; jj < 2; jj++)
                Ps[(tx * 2 + jj) * 64 + ty * 4 + ii] = sreg[ii][jj];
        __syncthreads();

        // ---- load V tile (reuse KV buffer) ----
        for (int idx = tid; idx < 32 * 64; idx += 256) {
            int r = idx >> 6, c = idx & 63;
            KV[r * 64 + c] = g_v[(size_t)(j * 32 + r) * 512 + g * HD + c];
        }
        // ---- online softmax row pass ----
        if (tid < 64) {
            const int r = tid;
            float m_old = rowM[r];
            float mx = m_old;
            #pragma unroll 8
            for (int c = 0; c < 32; c++) mx = fmaxf(mx, Ps[c * 64 + r]);
            float alpha = __expf(m_old - mx);
            float l = rowL[r] * alpha;
            #pragma unroll 8
            for (int c = 0; c < 32; c++) {
                float sv = Ps[c * 64 + r];
                float p = (sv < -1e29f) ? 0.0f : __expf(sv - mx);
                Ps[c * 64 + r] = p;
                l += p;
            }
            rowM[r] = mx; rowL[r] = l; rowA[r] = alpha;
        }
        __syncthreads();

        // ---- rescale O, then O += P V ----
        float al[4];
        #pragma unroll
        for (int ii = 0; ii < 4; ii++) al[ii] = rowA[ty * 4 + ii];
        #pragma unroll
        for (int ii = 0; ii < 4; ii++)
            #pragma unroll
            for (int jj = 0; jj < 4; jj++) o[ii][jj] *= al[ii];

        #pragma unroll 8
        for (int kk = 0; kk < 32; kk++) {
            float4 p4 = *(const float4*)&Ps[kk * 64 + ty * 4];
            float4 v4 = *(const float4*)&KV[kk * 64 + tx * 4];
            o[0][0] = fmaf(p4.x, v4.x, o[0][0]); o[0][1] = fmaf(p4.x, v4.y, o[0][1]);
            o[0][2] = fmaf(p4.x, v4.z, o[0][2]); o[0][3] = fmaf(p4.x, v4.w, o[0][3]);
            o[1][0] = fmaf(p4.y, v4.x, o[1][0]); o[1][1] = fmaf(p4.y, v4.y, o[1][1]);
            o[1][2] = fmaf(p4.y, v4.z, o[1][2]); o[1][3] = fmaf(p4.y, v4.w, o[1][3]);
            o[2][0] = fmaf(p4.z, v4.x, o[2][0]); o[2][1] = fmaf(p4.z, v4.y, o[2][1]);
            o[2][2] = fmaf(p4.z, v4.z, o[2][2]); o[2][3] = fmaf(p4.z, v4.w, o[2][3]);
            o[3][0] = fmaf(p4.w, v4.x, o[3][0]); o[3][1] = fmaf(p4.w, v4.y, o[3][1]);
            o[3][2] = fmaf(p4.w, v4.z, o[3][2]); o[3][3] = fmaf(p4.w, v4.w, o[3][3]);
        }
        __syncthreads();
    }

    // ---- epilogue: divide by l, write out ----
    #pragma unroll
    for (int ii = 0; ii < 4; ii++) {
        float linv = 1.0f / rowL[ty * 4 + ii];
        float* orow = g_attn + (size_t)(i * 64 + ty * 4 + ii) * HID + h * HD + tx * 4;
        *(float4*)orow = make_float4(o[ii][0] * linv, o[ii][1] * linv,
                                     o[ii][2] * linv, o[ii][3] * linv);
    }
}

// ================= launch =================
extern "C" void kernel_launch(void* const* d_in, const int* in_sizes, int n_in,
                              void* d_out, int out_size) {
    const float* hs     = (const float*)d_in[0];
    const float* q_w    = (const float*)d_in[1];
    const float* kr_w   = (const float*)d_in[2];
    const float* down_w = (const float*)d_in[3];
    const float* upk_w  = (const float*)d_in[4];
    const float* upv_w  = (const float*)d_in[5];
    const float* o_w    = (const float*)d_in[6];
    float* out = (float*)d_out;

    float *q, *kr, *ckv, *kc, *v, *attn;
    cudaGetSymbolAddress((void**)&q,    g_q);
    cudaGetSymbolAddress((void**)&kr,   g_kr);
    cudaGetSymbolAddress((void**)&ckv,  g_ckv);
    cudaGetSymbolAddress((void**)&kc,   g_kc);
    cudaGetSymbolAddress((void**)&v,    g_v);
    cudaGetSymbolAddress((void**)&attn, g_attn);

    // input projections
    sgemm_nt<<<dim3(HID / BN, S_LEN / BM), 256>>>(hs, q_w,    q,   S_LEN, HID, HID);
    sgemm_nt<<<dim3(256 / BN, S_LEN / BM), 256>>>(hs, kr_w,   kr,  S_LEN, 256, HID);
    sgemm_nt<<<dim3(256 / BN, S_LEN / BM), 256>>>(hs, down_w, ckv, S_LEN, 256, HID);
    // up projections
    sgemm_nt<<<dim3(256 / BN, S_LEN / BM), 256>>>(ckv, upk_w, kc, S_LEN, 256, 256);
    sgemm_nt<<<dim3(512 / BN, S_LEN / BM), 256>>>(ckv, upv_w, v,  S_LEN, 512, 256);
    // rope + key assembly
    rope_q_kernel<<<S_LEN, 1024>>>();
    make_kf_kernel<<<S_LEN, 512>>>();
    // attention
    flash_attn_kernel<<<dim3(32, NH), 256>>>();
    // output projection
    sgemm_nt<<<dim3(HID / BN, S_LEN / BM), 256>>>(attn, o_w, out, S_LEN, HID, NH * HD);
}

// round 4
// speedup vs baseline: 2.9741x; 2.9741x over previous
#include <cuda_runtime.h>
#include <math.h>
#include <stdint.h>

#define S_LEN 2048
#define HID   2048
#define NH    32
#define NKV   8
#define HD    64

// -------- scratch (no allocations allowed) --------
__device__ float g_q   [S_LEN * HID];    // q projection, roped in place
__device__ float g_kr  [S_LEN * 256];    // roped K components (pre-rotation)
__device__ float g_ckv [S_LEN * 256];    // latent
__device__ float g_kc  [S_LEN * 256];    // nope keys (up-proj)
__device__ float g_v   [S_LEN * 512];    // values [s, NKV*HD]
__device__ float g_kf  [S_LEN * 512];    // assembled full keys [s, NKV*HD]
__device__ float g_attn[S_LEN * HID];    // attention output

// ---------------- tf32 helpers ----------------
__device__ __forceinline__ float to_tf32(float x) {
    uint32_t y;
    asm("cvt.rna.tf32.f32 %0, %1;" : "=r"(y) : "f"(x));
    return __uint_as_float(y);
}

__device__ __forceinline__ void mma_tf32(float* c, const uint32_t* a, const uint32_t* b) {
    asm volatile(
        "mma.sync.aligned.m16n8k8.row.col.f32.tf32.tf32.f32 "
        "{%0,%1,%2,%3}, {%4,%5,%6,%7}, {%8,%9}, {%0,%1,%2,%3};\n"
        : "+f"(c[0]), "+f"(c[1]), "+f"(c[2]), "+f"(c[3])
        : "r"(a[0]), "r"(a[1]), "r"(a[2]), "r"(a[3]), "r"(b[0]), "r"(b[1]));
}

// ================= tf32 tensor-core GEMM: C[M,N] = A[M,K] * B[N,K]^T =================
// Requires M%128==0, N%128==0, K%32==0.
// Block 256 thr = 8 warps; block tile 128x128; warp owns 16 rows x 128 cols.
// smem stride 36 floats -> all fragment LDS are 32-bank conflict-free.
__global__ __launch_bounds__(256) void gemm_tf32(const float* __restrict__ A,
                                                 const float* __restrict__ B,
                                                 float* __restrict__ C,
                                                 int M, int N, int K) {
    __shared__ float As[128 * 36];
    __shared__ float Bs[128 * 36];

    const int tid  = threadIdx.x;
    const int warp = tid >> 5;
    const int lane = tid & 31;
    const int grp  = lane >> 2;    // 0..7
    const int tig  = lane & 3;     // 0..3
    const int m0   = blockIdx.y * 128;
    const int n0   = blockIdx.x * 128;
    const int wrow = warp * 16;

    const int lr = tid >> 1;           // 0..127
    const int lc = (tid & 1) * 16;     // 0 or 16

    float c[16][4];
    #pragma unroll
    for (int nt = 0; nt < 16; nt++)
        #pragma unroll
        for (int q = 0; q < 4; q++) c[nt][q] = 0.0f;

    for (int k0 = 0; k0 < K; k0 += 32) {
        const float* Ag = A + (size_t)(m0 + lr) * K + k0 + lc;
        const float* Bg = B + (size_t)(n0 + lr) * K + k0 + lc;
        #pragma unroll
        for (int q = 0; q < 4; q++) {
            float4 a4 = *(const float4*)(Ag + 4 * q);
            float4 b4 = *(const float4*)(Bg + 4 * q);
            a4.x = to_tf32(a4.x); a4.y = to_tf32(a4.y);
            a4.z = to_tf32(a4.z); a4.w = to_tf32(a4.w);
            b4.x = to_tf32(b4.x); b4.y = to_tf32(b4.y);
            b4.z = to_tf32(b4.z); b4.w = to_tf32(b4.w);
            *(float4*)&As[lr * 36 + lc + 4 * q] = a4;
            *(float4*)&Bs[lr * 36 + lc + 4 * q] = b4;
        }
        __syncthreads();

        #pragma unroll
        for (int kst = 0; kst < 4; kst++) {
            const int kk = kst * 8;
            uint32_t a[4];
            a[0] = __float_as_uint(As[(wrow + grp) * 36 + kk + tig]);
            a[1] = __float_as_uint(As[(wrow + grp + 8) * 36 + kk + tig]);
            a[2] = __float_as_uint(As[(wrow + grp) * 36 + kk + tig + 4]);
            a[3] = __float_as_uint(As[(wrow + grp + 8) * 36 + kk + tig + 4]);
            #pragma unroll
            for (int nt = 0; nt < 16; nt++) {
                uint32_t b[2];
                b[0] = __float_as_uint(Bs[(nt * 8 + grp) * 36 + kk + tig]);
                b[1] = __float_as_uint(Bs[(nt * 8 + grp) * 36 + kk + tig + 4]);
                mma_tf32(c[nt], a, b);
            }
        }
        __syncthreads();
    }

    #pragma unroll
    for (int nt = 0; nt < 16; nt++) {
        *(float2*)(C + (size_t)(m0 + wrow + grp) * N + n0 + nt * 8 + tig * 2) =
            make_float2(c[nt][0], c[nt][1]);
        *(float2*)(C + (size_t)(m0 + wrow + grp + 8) * N + n0 + nt * 8 + tig * 2) =
            make_float2(c[nt][2], c[nt][3]);
    }
}

// ================= RoPE on q (in place) =================
__global__ void rope_q_kernel() {
    const int s = blockIdx.x;
    const int t = threadIdx.x;
    const int h = t >> 5;       // head
    const int j = t & 31;       // rotation pair index (freq index)
    float inv = powf(10000.0f, -(float)j * (1.0f / 32.0f));
    float sn, cs;
    sincosf((float)s * inv, &sn, &cs);
    float* q = g_q + (size_t)s * HID + h * HD;
    float x = q[j];
    float y = q[j + 32];
    q[j]      = x * cs - y * sn;
    q[j + 32] = y * cs + x * sn;
}

// ================= assemble full key =================
__global__ void make_kf_kernel() {
    const int s = blockIdx.x;
    const int t = threadIdx.x;   // 512
    const int g = t >> 6;
    const int d = t & 63;
    const int j = d & 31;
    float out;
    if (j < 16) {
        const int selfc = g * 32 + ((d < 32) ? j : 16 + j);
        const int partc = g * 32 + ((d < 32) ? 16 + j : j);
        float inv = powf(10000.0f, -(float)j * (1.0f / 32.0f));
        float sn, cs;
        sincosf((float)s * inv, &sn, &cs);
        float x = g_kr[(size_t)s * 256 + selfc];
        float y = g_kr[(size_t)s * 256 + partc];
        out = (d < 32) ? (x * cs - y * sn) : (x * cs + y * sn);
    } else {
        const int cc = g * 32 + ((d < 32) ? (d - 16) : (d - 32));
        out = g_kc[(size_t)s * 256 + cc];
    }
    g_kf[(size_t)s * 512 + g * HD + d] = out;
}

// ================= tf32 flash attention =================
// Block = (128-row q tile, head); 8 warps x 16 rows. K/V tiles of 64 keys.
// smem (floats): Qs[128*68] @0, Ks[64*68] @8704, Vs[64*72] @13056, Ps[128*68] @17664.
// Total 26368 floats = 105472 bytes (dynamic).
#define FA_SMEM_BYTES 105472

__global__ __launch_bounds__(256) void flash_tf32() {
    extern __shared__ float sm[];
    float* Qs = sm;              // [q][d]   stride 68
    float* Ks = sm + 8704;       // [key][d] stride 68
    float* Vs = sm + 13056;      // [key][d] stride 72
    float* Ps = sm + 17664;      // [q][key] stride 68

    const int h = blockIdx.y;
    const int i = 15 - (int)blockIdx.x;   // heavy tiles first
    const int g = h >> 2;                 // kv head

    const int tid  = threadIdx.x;
    const int warp = tid >> 5;
    const int lane = tid & 31;
    const int grp  = lane >> 2;
    const int tig  = lane & 3;
    const int wrow = warp * 16;

    // load Q tile (pre-scaled, tf32)
    for (int idx = tid; idx < 128 * 64; idx += 256) {
        int r = idx >> 6, d = idx & 63;
        Qs[r * 68 + d] = to_tf32(g_q[(size_t)(i * 128 + r) * HID + h * HD + d] * 0.125f);
    }

    float o[8][4];
    #pragma unroll
    for (int nt = 0; nt < 8; nt++)
        #pragma unroll
        for (int q = 0; q < 4; q++) o[nt][q] = 0.0f;

    float m_lo = -1e30f, m_hi = -1e30f;
    float l_lo = 0.0f,   l_hi = 0.0f;

    const int row_lo = i * 128 + wrow + grp;
    const int row_hi = row_lo + 8;

    const int ntiles = 2 * i + 2;
    for (int j = 0; j < ntiles; j++) {
        // ---- load K, V tiles ----
        for (int idx = tid; idx < 64 * 64; idx += 256) {
            int r = idx >> 6, d = idx & 63;
            Ks[r * 68 + d] = to_tf32(g_kf[(size_t)(j * 64 + r) * 512 + g * HD + d]);
            Vs[r * 72 + d] = to_tf32(g_v [(size_t)(j * 64 + r) * 512 + g * HD + d]);
        }
        __syncthreads();

        // ---- S = Q K^T (warp strip: 16 rows x 64 keys) ----
        float s[8][4];
        #pragma unroll
        for (int nt = 0; nt < 8; nt++)
            #pragma unroll
            for (int q = 0; q < 4; q++) s[nt][q] = 0.0f;

        #pragma unroll
        for (int kst = 0; kst < 8; kst++) {
            const int kk = kst * 8;
            uint32_t a[4];
            a[0] = __float_as_uint(Qs[(wrow + grp) * 68 + kk + tig]);
            a[1] = __float_as_uint(Qs[(wrow + grp + 8) * 68 + kk + tig]);
            a[2] = __float_as_uint(Qs[(wrow + grp) * 68 + kk + tig + 4]);
            a[3] = __float_as_uint(Qs[(wrow + grp + 8) * 68 + kk + tig + 4]);
            #pragma unroll
            for (int nt = 0; nt < 8; nt++) {
                uint32_t b[2];
                b[0] = __float_as_uint(Ks[(nt * 8 + grp) * 68 + kk + tig]);
                b[1] = __float_as_uint(Ks[(nt * 8 + grp) * 68 + kk + tig + 4]);
                mma_tf32(s[nt], a, b);
            }
        }

        // ---- causal mask ----
        if (j * 64 + 63 > row_lo) {
            #pragma unroll
            for (int nt = 0; nt < 8; nt++) {
                const int col0 = j * 64 + nt * 8 + 2 * tig;
                if (col0     > row_lo) s[nt][0] = -1e30f;
                if (col0 + 1 > row_lo) s[nt][1] = -1e30f;
                if (col0     > row_hi) s[nt][2] = -1e30f;
                if (col0 + 1 > row_hi) s[nt][3] = -1e30f;
            }
        }

        // ---- online softmax (warp-local) ----
        float tlo = -1e30f, thi = -1e30f;
        #pragma unroll
        for (int nt = 0; nt < 8; nt++) {
            tlo = fmaxf(tlo, fmaxf(s[nt][0], s[nt][1]));
            thi = fmaxf(thi, fmaxf(s[nt][2], s[nt][3]));
        }
        tlo = fmaxf(tlo, __shfl_xor_sync(0xffffffff, tlo, 1));
        tlo = fmaxf(tlo, __shfl_xor_sync(0xffffffff, tlo, 2));
        thi = fmaxf(thi, __shfl_xor_sync(0xffffffff, thi, 1));
        thi = fmaxf(thi, __shfl_xor_sync(0xffffffff, thi, 2));

        const float mnl = fmaxf(m_lo, tlo);
        const float mnh = fmaxf(m_hi, thi);
        const float alo = __expf(m_lo - mnl);
        const float ahi = __expf(m_hi - mnh);

        float slo = 0.0f, shi = 0.0f;
        #pragma unroll
        for (int nt = 0; nt < 8; nt++) {
            const float p0 = __expf(s[nt][0] - mnl);
            const float p1 = __expf(s[nt][1] - mnl);
            const float p2 = __expf(s[nt][2] - mnh);
            const float p3 = __expf(s[nt][3] - mnh);
            slo += p0 + p1;
            shi += p2 + p3;
            *(float2*)&Ps[(wrow + grp) * 68 + nt * 8 + 2 * tig] =
                make_float2(to_tf32(p0), to_tf32(p1));
            *(float2*)&Ps[(wrow + grp + 8) * 68 + nt * 8 + 2 * tig] =
                make_float2(to_tf32(p2), to_tf32(p3));
        }
        slo += __shfl_xor_sync(0xffffffff, slo, 1);
        slo += __shfl_xor_sync(0xffffffff, slo, 2);
        shi += __shfl_xor_sync(0xffffffff, shi, 1);
        shi += __shfl_xor_sync(0xffffffff, shi, 2);

        l_lo = l_lo * alo + slo;
        l_hi = l_hi * ahi + shi;
        m_lo = mnl; m_hi = mnh;

        #pragma unroll
        for (int nt = 0; nt < 8; nt++) {
            o[nt][0] *= alo; o[nt][1] *= alo;
            o[nt][2] *= ahi; o[nt][3] *= ahi;
        }
        __syncwarp();

        // ---- O += P V ----
        #pragma unroll
        for (int kst = 0; kst < 8; kst++) {
            const int kk = kst * 8;
            uint32_t a[4];
            a[0] = __float_as_uint(Ps[(wrow + grp) * 68 + kk + tig]);
            a[1] = __float_as_uint(Ps[(wrow + grp + 8) * 68 + kk + tig]);
            a[2] = __float_as_uint(Ps[(wrow + grp) * 68 + kk + tig + 4]);
            a[3] = __float_as_uint(Ps[(wrow + grp + 8) * 68 + kk + tig + 4]);
            #pragma unroll
            for (int nt = 0; nt < 8; nt++) {
                uint32_t b[2];
                b[0] = __float_as_uint(Vs[(kk + tig) * 72 + nt * 8 + grp]);
                b[1] = __float_as_uint(Vs[(kk + tig + 4) * 72 + nt * 8 + grp]);
                mma_tf32(o[nt], a, b);
            }
        }
        __syncthreads();
    }

    // ---- epilogue ----
    const float inv_lo = 1.0f / l_lo;
    const float inv_hi = 1.0f / l_hi;
    #pragma unroll
    for (int nt = 0; nt < 8; nt++) {
        const int col = h * HD + nt * 8 + 2 * tig;
        *(float2*)&g_attn[(size_t)row_lo * HID + col] =
            make_float2(o[nt][0] * inv_lo, o[nt][1] * inv_lo);
        *(float2*)&g_attn[(size_t)row_hi * HID + col] =
            make_float2(o[nt][2] * inv_hi, o[nt][3] * inv_hi);
    }
}

// ================= launch =================
extern "C" void kernel_launch(void* const* d_in, const int* in_sizes, int n_in,
                              void* d_out, int out_size) {
    const float* hs     = (const float*)d_in[0];
    const float* q_w    = (const float*)d_in[1];
    const float* kr_w   = (const float*)d_in[2];
    const float* down_w = (const float*)d_in[3];
    const float* upk_w  = (const float*)d_in[4];
    const float* upv_w  = (const float*)d_in[5];
    const float* o_w    = (const float*)d_in[6];
    float* out = (float*)d_out;

    float *q, *kr, *ckv, *kc, *v, *attn;
    cudaGetSymbolAddress((void**)&q,    g_q);
    cudaGetSymbolAddress((void**)&kr,   g_kr);
    cudaGetSymbolAddress((void**)&ckv,  g_ckv);
    cudaGetSymbolAddress((void**)&kc,   g_kc);
    cudaGetSymbolAddress((void**)&v,    g_v);
    cudaGetSymbolAddress((void**)&attn, g_attn);

    // idempotent, deterministic — called every launch (no static guards allowed)
    cudaFuncSetAttribute(flash_tf32, cudaFuncAttributeMaxDynamicSharedMemorySize,
                         FA_SMEM_BYTES);

    // input projections
    gemm_tf32<<<dim3(HID / 128, S_LEN / 128), 256>>>(hs, q_w,    q,   S_LEN, HID, HID);
    gemm_tf32<<<dim3(256 / 128, S_LEN / 128), 256>>>(hs, kr_w,   kr,  S_LEN, 256, HID);
    gemm_tf32<<<dim3(256 / 128, S_LEN / 128), 256>>>(hs, down_w, ckv, S_LEN, 256, HID);
    // up projections
    gemm_tf32<<<dim3(256 / 128, S_LEN / 128), 256>>>(ckv, upk_w, kc, S_LEN, 256, 256);
    gemm_tf32<<<dim3(512 / 128, S_LEN / 128), 256>>>(ckv, upv_w, v,  S_LEN, 512, 256);
    // rope + key assembly
    rope_q_kernel<<<S_LEN, 1024>>>();
    make_kf_kernel<<<S_LEN, 512>>>();
    // attention
    flash_tf32<<<dim3(16, NH), 256, FA_SMEM_BYTES>>>();
    // output projection
    gemm_tf32<<<dim3(HID / 128, S_LEN / 128), 256>>>(attn, o_w, out, S_LEN, HID, NH * HD);
}

// round 5
// speedup vs baseline: 6.8574x; 2.3057x over previous
#include <cuda_runtime.h>
#include <cuda_fp16.h>
#include <math.h>
#include <stdint.h>

#define S_LEN 2048
#define HID   2048
#define NH    32
#define NKV   8
#define HD    64

// -------- half-precision scratch (no allocations allowed) --------
__device__ __half h_hs [4194304];
__device__ __half h_qw [4194304];
__device__ __half h_krw[524288];
__device__ __half h_dw [524288];
__device__ __half h_ukw[65536];
__device__ __half h_uvw[131072];
__device__ __half h_ow [4194304];

__device__ __half g_q   [4194304];   // q projection (roped+scaled in place)
__device__ __half g_kr  [524288];    // roped K components (pre-rotation)
__device__ __half g_ckv [524288];    // latent
__device__ __half g_kc  [524288];    // nope keys
__device__ __half g_vT  [1048576];   // values TRANSPOSED [NKV*HD][S]
__device__ __half g_kf  [1048576];   // assembled keys [S][NKV*HD]
__device__ __half g_attn[4194304];   // attention output [S][NH*HD]

// ---------------- helpers ----------------
__device__ __forceinline__ void cpa16(const void* g, void* s) {
    uint32_t sa = (uint32_t)__cvta_generic_to_shared(s);
    asm volatile("cp.async.cg.shared.global [%0], [%1], 16;\n" :: "r"(sa), "l"(g));
}
#define CP_COMMIT asm volatile("cp.async.commit_group;\n" ::: "memory")
#define CP_WAIT0  asm volatile("cp.async.wait_group 0;\n" ::: "memory")

__device__ __forceinline__ void mma_f16(float* c, uint32_t a0, uint32_t a1,
                                        uint32_t a2, uint32_t a3,
                                        uint32_t b0, uint32_t b1) {
    asm volatile(
        "mma.sync.aligned.m16n8k16.row.col.f32.f16.f16.f32 "
        "{%0,%1,%2,%3}, {%4,%5,%6,%7}, {%8,%9}, {%0,%1,%2,%3};\n"
        : "+f"(c[0]), "+f"(c[1]), "+f"(c[2]), "+f"(c[3])
        : "r"(a0), "r"(a1), "r"(a2), "r"(a3), "r"(b0), "r"(b1));
}

__device__ __forceinline__ uint32_t packh2(float x, float y) {
    __half2 h = __floats2half2_rn(x, y);
    return *(uint32_t*)&h;
}

// ================= f32 -> f16 conversion of all inputs (single kernel) =================
__global__ void cvt_all(const float* __restrict__ hs, const float* __restrict__ qw,
                        const float* __restrict__ krw, const float* __restrict__ dw,
                        const float* __restrict__ uk,  const float* __restrict__ uv,
                        const float* __restrict__ ow) {
    size_t i = (size_t)blockIdx.x * blockDim.x + threadIdx.x;  // half2 index
    const float2* src; __half2* dst; size_t off;
    if      (i < 2097152) { src = (const float2*)hs;  dst = (__half2*)h_hs;  off = i; }
    else if (i < 4194304) { src = (const float2*)qw;  dst = (__half2*)h_qw;  off = i - 2097152; }
    else if (i < 4456448) { src = (const float2*)krw; dst = (__half2*)h_krw; off = i - 4194304; }
    else if (i < 4718592) { src = (const float2*)dw;  dst = (__half2*)h_dw;  off = i - 4456448; }
    else if (i < 4751360) { src = (const float2*)uk;  dst = (__half2*)h_ukw; off = i - 4718592; }
    else if (i < 4816896) { src = (const float2*)uv;  dst = (__half2*)h_uvw; off = i - 4751360; }
    else if (i < 6914048) { src = (const float2*)ow;  dst = (__half2*)h_ow;  off = i - 4816896; }
    else return;
    float2 v = src[off];
    dst[off] = __floats2half2_rn(v.x, v.y);
}

// ================= fp16 tensor-core GEMM: C[M,N] = A[M,K]*B[N,K]^T =================
// Block 128x128, K-tile 32, cp.async double-buffered. 8 warps = 4(m) x 2(n),
// warp tile 32x64. smem rows padded to 40 halves (conflict-free 32-bit frag loads).
template<typename OutT, bool TRANS>
__global__ __launch_bounds__(256) void gemm_h(const __half* __restrict__ A,
                                              const __half* __restrict__ B,
                                              OutT* __restrict__ C,
                                              int M, int N, int K) {
    __shared__ __align__(16) __half As[2][128 * 40];
    __shared__ __align__(16) __half Bs[2][128 * 40];

    const int tid  = threadIdx.x;
    const int warp = tid >> 5, lane = tid & 31;
    const int grp  = lane >> 2, tig = lane & 3;
    const int m0   = blockIdx.y * 128, n0 = blockIdx.x * 128;
    const int wm   = (warp & 3) * 32, wn = (warp >> 2) * 64;

    float c[2][8][4] = {};

    const int T = K >> 5;

    auto issue = [&](int t, int buf) {
        const __half* Ag = A + (size_t)m0 * K + t * 32;
        const __half* Bg = B + (size_t)n0 * K + t * 32;
        #pragma unroll
        for (int q = 0; q < 2; q++) {
            int ch = tid + q * 256;          // 0..511: row=ch>>2, seg=ch&3
            int r = ch >> 2, sg = ch & 3;
            cpa16(Ag + (size_t)r * K + sg * 8, &As[buf][r * 40 + sg * 8]);
            cpa16(Bg + (size_t)r * K + sg * 8, &Bs[buf][r * 40 + sg * 8]);
        }
    };

    issue(0, 0); CP_COMMIT;

    for (int t = 0; t < T; t++) {
        CP_WAIT0;
        __syncthreads();
        if (t + 1 < T) { issue(t + 1, (t + 1) & 1); CP_COMMIT; }
        const __half* as = As[t & 1];
        const __half* bs = Bs[t & 1];
        #pragma unroll
        for (int ks = 0; ks < 2; ks++) {
            const int kb = ks * 16;
            uint32_t a[2][4];
            #pragma unroll
            for (int mt = 0; mt < 2; mt++) {
                int r = wm + mt * 16 + grp;
                a[mt][0] = *(const uint32_t*)&as[r * 40 + kb + 2 * tig];
                a[mt][1] = *(const uint32_t*)&as[(r + 8) * 40 + kb + 2 * tig];
                a[mt][2] = *(const uint32_t*)&as[r * 40 + kb + 2 * tig + 8];
                a[mt][3] = *(const uint32_t*)&as[(r + 8) * 40 + kb + 2 * tig + 8];
            }
            #pragma unroll
            for (int nt = 0; nt < 8; nt++) {
                int cl = wn + nt * 8 + grp;
                uint32_t b0 = *(const uint32_t*)&bs[cl * 40 + kb + 2 * tig];
                uint32_t b1 = *(const uint32_t*)&bs[cl * 40 + kb + 2 * tig + 8];
                mma_f16(c[0][nt], a[0][0], a[0][1], a[0][2], a[0][3], b0, b1);
                mma_f16(c[1][nt], a[1][0], a[1][1], a[1][2], a[1][3], b0, b1);
            }
        }
    }

    #pragma unroll
    for (int mt = 0; mt < 2; mt++) {
        const int r_0 = m0 + wm + mt * 16 + grp;
        const int r_1 = r_0 + 8;
        #pragma unroll
        for (int nt = 0; nt < 8; nt++) {
            const int cc = n0 + wn + nt * 8 + 2 * tig;
            if constexpr (TRANS) {
                // C is [N][M] halves
                __half* Ch = (__half*)C;
                Ch[(size_t)cc * M + r_0]       = __float2half_rn(c[mt][nt][0]);
                Ch[(size_t)(cc + 1) * M + r_0] = __float2half_rn(c[mt][nt][1]);
                Ch[(size_t)cc * M + r_1]       = __float2half_rn(c[mt][nt][2]);
                Ch[(size_t)(cc + 1) * M + r_1] = __float2half_rn(c[mt][nt][3]);
            } else if constexpr (sizeof(OutT) == 4) {
                *(float2*)((float*)C + (size_t)r_0 * N + cc) =
                    make_float2(c[mt][nt][0], c[mt][nt][1]);
                *(float2*)((float*)C + (size_t)r_1 * N + cc) =
                    make_float2(c[mt][nt][2], c[mt][nt][3]);
            } else {
                *(__half2*)((__half*)C + (size_t)r_0 * N + cc) =
                    __floats2half2_rn(c[mt][nt][0], c[mt][nt][1]);
                *(__half2*)((__half*)C + (size_t)r_1 * N + cc) =
                    __floats2half2_rn(c[mt][nt][2], c[mt][nt][3]);
            }
        }
    }
}

// ================= RoPE on q (in place, fold softmax scale 0.125) =================
__global__ void rope_q_kernel() {
    const int s = blockIdx.x;
    const int t = threadIdx.x;
    const int h = t >> 5;
    const int j = t & 31;
    float inv = powf(10000.0f, -(float)j * (1.0f / 32.0f));
    float sn, cs;
    sincosf((float)s * inv, &sn, &cs);
    __half* q = g_q + (size_t)s * HID + h * HD;
    float x = __half2float(q[j]);
    float y = __half2float(q[j + 32]);
    q[j]      = __float2half_rn(0.125f * (x * cs - y * sn));
    q[j + 32] = __float2half_rn(0.125f * (y * cs + x * sn));
}

// ================= assemble full key (half) =================
__global__ void make_kf_kernel() {
    const int s = blockIdx.x;
    const int t = threadIdx.x;   // 512
    const int g = t >> 6;
    const int d = t & 63;
    const int j = d & 31;
    float out;
    if (j < 16) {
        const int selfc = g * 32 + ((d < 32) ? j : 16 + j);
        const int partc = g * 32 + ((d < 32) ? 16 + j : j);
        float inv = powf(10000.0f, -(float)j * (1.0f / 32.0f));
        float sn, cs;
        sincosf((float)s * inv, &sn, &cs);
        float x = __half2float(g_kr[(size_t)s * 256 + selfc]);
        float y = __half2float(g_kr[(size_t)s * 256 + partc]);
        out = (d < 32) ? (x * cs - y * sn) : (x * cs + y * sn);
    } else {
        const int cc = g * 32 + ((d < 32) ? (d - 16) : (d - 32));
        out = __half2float(g_kc[(size_t)s * 256 + cc]);
    }
    g_kf[(size_t)s * 512 + g * HD + d] = __float2half_rn(out);
}

// ================= fp16 flash attention =================
// Block = (128-row q tile, head); 8 warps x 16 rows; 64-key K/V tiles,
// cp.async double-buffered; P stays in registers (S-frag == A-frag layout).
// smem halves: Qs[128*72] @0 | Ks[2][64*72] @9216 | Vs[2][64*72] @18432
#define FA_SMEM_BYTES 55296

__global__ __launch_bounds__(256) void flash_h() {
    extern __shared__ __align__(16) __half smh[];
    __half* Qs  = smh;
    __half* Ks0 = smh + 9216;
    __half* Ks1 = Ks0 + 4608;
    __half* Vs0 = smh + 18432;
    __half* Vs1 = Vs0 + 4608;

    const int h = blockIdx.y;
    const int i = 15 - (int)blockIdx.x;   // heavy tiles first
    const int g = h >> 2;

    const int tid  = threadIdx.x;
    const int warp = tid >> 5, lane = tid & 31;
    const int grp  = lane >> 2, tig = lane & 3;
    const int wrow = warp * 16;

    auto issueKV = [&](int j, int buf) {
        __half* kd = buf ? Ks1 : Ks0;
        __half* vd = buf ? Vs1 : Vs0;
        const __half* kg = g_kf + (size_t)(j * 64) * 512 + g * 64;
        const __half* vg = g_vT + (size_t)(g * 64) * 2048 + j * 64;
        #pragma unroll
        for (int q = 0; q < 2; q++) {
            int ch = tid + q * 256;          // 0..511: row=ch>>3, seg=ch&7
            int r = ch >> 3, sg = ch & 7;
            cpa16(kg + (size_t)r * 512 + sg * 8,  &kd[r * 72 + sg * 8]);
            cpa16(vg + (size_t)r * 2048 + sg * 8, &vd[r * 72 + sg * 8]);
        }
    };

    // prologue: Q tile + first K/V tile in one group
    {
        const __half* qg = g_q + (size_t)(i * 128) * 2048 + h * 64;
        for (int ch = tid; ch < 1024; ch += 256) {
            int r = ch >> 3, sg = ch & 7;
            cpa16(qg + (size_t)r * 2048 + sg * 8, &Qs[r * 72 + sg * 8]);
        }
        issueKV(0, 0);
        CP_COMMIT;
    }

    float o[8][4] = {};
    float m_lo = -1e30f, m_hi = -1e30f, l_lo = 0.0f, l_hi = 0.0f;
    const int row_lo = i * 128 + wrow + grp;
    const int row_hi = row_lo + 8;

    const int ntiles = 2 * i + 2;
    for (int j = 0; j < ntiles; j++) {
        CP_WAIT0;
        __syncthreads();
        if (j + 1 < ntiles) { issueKV(j + 1, (j + 1) & 1); CP_COMMIT; }
        const __half* ks = (j & 1) ? Ks1 : Ks0;
        const __half* vs = (j & 1) ? Vs1 : Vs0;

        // ---- S = Q K^T ----
        float s[8][4] = {};
        #pragma unroll
        for (int kst = 0; kst < 4; kst++) {
            const int kb = kst * 16;
            uint32_t a0 = *(const uint32_t*)&Qs[(wrow + grp) * 72 + kb + 2 * tig];
            uint32_t a1 = *(const uint32_t*)&Qs[(wrow + grp + 8) * 72 + kb + 2 * tig];
            uint32_t a2 = *(const uint32_t*)&Qs[(wrow + grp) * 72 + kb + 2 * tig + 8];
            uint32_t a3 = *(const uint32_t*)&Qs[(wrow + grp + 8) * 72 + kb + 2 * tig + 8];
            #pragma unroll
            for (int nt = 0; nt < 8; nt++) {
                uint32_t b0 = *(const uint32_t*)&ks[(nt * 8 + grp) * 72 + kb + 2 * tig];
                uint32_t b1 = *(const uint32_t*)&ks[(nt * 8 + grp) * 72 + kb + 2 * tig + 8];
                mma_f16(s[nt], a0, a1, a2, a3, b0, b1);
            }
        }

        // ---- causal mask ----
        if (j * 64 + 63 > row_lo) {
            #pragma unroll
            for (int nt = 0; nt < 8; nt++) {
                const int col0 = j * 64 + nt * 8 + 2 * tig;
                if (col0     > row_lo) s[nt][0] = -1e30f;
                if (col0 + 1 > row_lo) s[nt][1] = -1e30f;
                if (col0     > row_hi) s[nt][2] = -1e30f;
                if (col0 + 1 > row_hi) s[nt][3] = -1e30f;
            }
        }

        // ---- online softmax (warp-local), pack P into A-fragments ----
        float tlo = -1e30f, thi = -1e30f;
        #pragma unroll
        for (int nt = 0; nt < 8; nt++) {
            tlo = fmaxf(tlo, fmaxf(s[nt][0], s[nt][1]));
            thi = fmaxf(thi, fmaxf(s[nt][2], s[nt][3]));
        }
        tlo = fmaxf(tlo, __shfl_xor_sync(0xffffffff, tlo, 1));
        tlo = fmaxf(tlo, __shfl_xor_sync(0xffffffff, tlo, 2));
        thi = fmaxf(thi, __shfl_xor_sync(0xffffffff, thi, 1));
        thi = fmaxf(thi, __shfl_xor_sync(0xffffffff, thi, 2));

        const float mnl = fmaxf(m_lo, tlo);
        const float mnh = fmaxf(m_hi, thi);
        const float alo = __expf(m_lo - mnl);
        const float ahi = __expf(m_hi - mnh);

        uint32_t ph[8][2];
        float slo = 0.0f, shi = 0.0f;
        #pragma unroll
        for (int nt = 0; nt < 8; nt++) {
            const float p0 = __expf(s[nt][0] - mnl);
            const float p1 = __expf(s[nt][1] - mnl);
            const float p2 = __expf(s[nt][2] - mnh);
            const float p3 = __expf(s[nt][3] - mnh);
            slo += p0 + p1;
            shi += p2 + p3;
            ph[nt][0] = packh2(p0, p1);
            ph[nt][1] = packh2(p2, p3);
        }
        slo += __shfl_xor_sync(0xffffffff, slo, 1);
        slo += __shfl_xor_sync(0xffffffff, slo, 2);
        shi += __shfl_xor_sync(0xffffffff, shi, 1);
        shi += __shfl_xor_sync(0xffffffff, shi, 2);

        l_lo = l_lo * alo + slo;
        l_hi = l_hi * ahi + shi;
        m_lo = mnl; m_hi = mnh;

        #pragma unroll
        for (int nt = 0; nt < 8; nt++) {
            o[nt][0] *= alo; o[nt][1] *= alo;
            o[nt][2] *= ahi; o[nt][3] *= ahi;
        }

        // ---- O += P V  (A-fragments straight from registers) ----
        #pragma unroll
        for (int j2 = 0; j2 < 4; j2++) {
            const int kb = j2 * 16;
            uint32_t a0 = ph[2 * j2][0],     a1 = ph[2 * j2][1];
            uint32_t a2 = ph[2 * j2 + 1][0], a3 = ph[2 * j2 + 1][1];
            #pragma unroll
            for (int nt = 0; nt < 8; nt++) {
                uint32_t b0 = *(const uint32_t*)&vs[(nt * 8 + grp) * 72 + kb + 2 * tig];
                uint32_t b1 = *(const uint32_t*)&vs[(nt * 8 + grp) * 72 + kb + 2 * tig + 8];
                mma_f16(o[nt], a0, a1, a2, a3, b0, b1);
            }
        }
    }

    // ---- epilogue ----
    const float inv_lo = 1.0f / l_lo;
    const float inv_hi = 1.0f / l_hi;
    #pragma unroll
    for (int nt = 0; nt < 8; nt++) {
        const int col = h * HD + nt * 8 + 2 * tig;
        *(__half2*)&g_attn[(size_t)row_lo * HID + col] =
            __floats2half2_rn(o[nt][0] * inv_lo, o[nt][1] * inv_lo);
        *(__half2*)&g_attn[(size_t)row_hi * HID + col] =
            __floats2half2_rn(o[nt][2] * inv_hi, o[nt][3] * inv_hi);
    }
}

// ================= launch =================
extern "C" void kernel_launch(void* const* d_in, const int* in_sizes, int n_in,
                              void* d_out, int out_size) {
    const float* hs     = (const float*)d_in[0];
    const float* q_w    = (const float*)d_in[1];
    const float* kr_w   = (const float*)d_in[2];
    const float* down_w = (const float*)d_in[3];
    const float* upk_w  = (const float*)d_in[4];
    const float* upv_w  = (const float*)d_in[5];
    const float* o_w    = (const float*)d_in[6];
    float* out = (float*)d_out;

    __half *p_hs, *p_qw, *p_krw, *p_dw, *p_ukw, *p_uvw, *p_ow;
    __half *p_q, *p_kr, *p_ckv, *p_kc, *p_vT, *p_attn;
    cudaGetSymbolAddress((void**)&p_hs,  h_hs);
    cudaGetSymbolAddress((void**)&p_qw,  h_qw);
    cudaGetSymbolAddress((void**)&p_krw, h_krw);
    cudaGetSymbolAddress((void**)&p_dw,  h_dw);
    cudaGetSymbolAddress((void**)&p_ukw, h_ukw);
    cudaGetSymbolAddress((void**)&p_uvw, h_uvw);
    cudaGetSymbolAddress((void**)&p_ow,  h_ow);
    cudaGetSymbolAddress((void**)&p_q,   g_q);
    cudaGetSymbolAddress((void**)&p_kr,  g_kr);
    cudaGetSymbolAddress((void**)&p_ckv, g_ckv);
    cudaGetSymbolAddress((void**)&p_kc,  g_kc);
    cudaGetSymbolAddress((void**)&p_vT,  g_vT);
    cudaGetSymbolAddress((void**)&p_attn, g_attn);

    cudaFuncSetAttribute(flash_h, cudaFuncAttributeMaxDynamicSharedMemorySize,
                         FA_SMEM_BYTES);

    // convert all fp32 inputs to fp16
    cvt_all<<<27008, 256>>>(hs, q_w, kr_w, down_w, upk_w, upv_w, o_w);

    // projections (fp16 mma, fp32 accumulate)
    gemm_h<__half, false><<<dim3(16, 16), 256>>>(p_hs,  p_qw,  p_q,   S_LEN, HID, HID);
    gemm_h<__half, false><<<dim3(2, 16),  256>>>(p_hs,  p_krw, p_kr,  S_LEN, 256, HID);
    gemm_h<__half, false><<<dim3(2, 16),  256>>>(p_hs,  p_dw,  p_ckv, S_LEN, 256, HID);
    gemm_h<__half, false><<<dim3(2, 16),  256>>>(p_ckv, p_ukw, p_kc,  S_LEN, 256, 256);
    gemm_h<__half, true ><<<dim3(4, 16),  256>>>(p_ckv, p_uvw, p_vT,  S_LEN, 512, 256);

    // rope + key assembly
    rope_q_kernel<<<S_LEN, 1024>>>();
    make_kf_kernel<<<S_LEN, 512>>>();

    // attention
    flash_h<<<dim3(16, NH), 256, FA_SMEM_BYTES>>>();

    // output projection (fp32 out)
    gemm_h<float, false><<<dim3(16, 16), 256>>>(p_attn, p_ow, out, S_LEN, HID, NH * HD);
}

// round 6
// speedup vs baseline: 9.0706x; 1.3228x over previous
#include <cuda_runtime.h>
#include <cuda_fp16.h>
#include <math.h>
#include <stdint.h>

#define S_LEN 2048
#define HID   2048
#define NH    32
#define NKV   8
#define HD    64

// -------- half scratch (no allocations allowed) --------
__device__ __half h_hs   [4194304];   // hidden states [2048][2048]
__device__ __half h_qw   [4194304];   // q_w [2048][2048]
__device__ __half h_krw  [524288];    // kr_w [256][2048]
__device__ __half h_dwT  [524288];    // down_w transposed [2048][256]
__device__ __half h_ukuv [196608];    // concat(upk_w, upv_w) [768][256]
__device__ __half h_wcomb[1572864];   // [upk;upv] @ down_w   [768][2048]
__device__ __half h_ow   [4194304];   // o_w [2048][2048]

__device__ __half g_q   [4194304];   // q projection (roped+scaled in place)
__device__ __half g_kr  [524288];    // roped K comps (pre-rotation) [S][256]
__device__ __half g_kc  [524288];    // nope keys [S][256]
__device__ __half g_vT  [1048576];   // values TRANSPOSED [512][S]
__device__ __half g_kf  [1048576];   // assembled keys [S][512]
__device__ __half g_attn[4194304];   // attention output [S][2048]

// ---------------- helpers ----------------
__device__ __forceinline__ void cpa16(const void* g, void* s) {
    uint32_t sa = (uint32_t)__cvta_generic_to_shared(s);
    asm volatile("cp.async.cg.shared.global [%0], [%1], 16;\n" :: "r"(sa), "l"(g));
}
#define CP_COMMIT asm volatile("cp.async.commit_group;\n" ::: "memory")
#define CP_WAIT0  asm volatile("cp.async.wait_group 0;\n" ::: "memory")

__device__ __forceinline__ void mma_f16(float* c, uint32_t a0, uint32_t a1,
                                        uint32_t a2, uint32_t a3,
                                        uint32_t b0, uint32_t b1) {
    asm volatile(
        "mma.sync.aligned.m16n8k16.row.col.f32.f16.f16.f32 "
        "{%0,%1,%2,%3}, {%4,%5,%6,%7}, {%8,%9}, {%0,%1,%2,%3};\n"
        : "+f"(c[0]), "+f"(c[1]), "+f"(c[2]), "+f"(c[3])
        : "r"(a0), "r"(a1), "r"(a2), "r"(a3), "r"(b0), "r"(b1));
}

__device__ __forceinline__ void ldsm4(uint32_t* r, const void* p) {
    uint32_t a = (uint32_t)__cvta_generic_to_shared(p);
    asm volatile("ldmatrix.sync.aligned.m8n8.x4.shared.b16 {%0,%1,%2,%3}, [%4];\n"
                 : "=r"(r[0]), "=r"(r[1]), "=r"(r[2]), "=r"(r[3]) : "r"(a));
}

__device__ __forceinline__ uint32_t packh2(float x, float y) {
    __half2 h = __floats2half2_rn(x, y);
    return *(uint32_t*)&h;
}

// ================= f32 -> f16 conversion / reshuffle of all inputs =================
__global__ void cvt_all(const float* __restrict__ hs, const float* __restrict__ qw,
                        const float* __restrict__ krw, const float* __restrict__ dw,
                        const float* __restrict__ uk,  const float* __restrict__ uv,
                        const float* __restrict__ ow) {
    size_t i = (size_t)blockIdx.x * blockDim.x + threadIdx.x;  // float2 work unit
    if (i < 2097152) {
        float2 v = ((const float2*)hs)[i];
        ((__half2*)h_hs)[i] = __floats2half2_rn(v.x, v.y);
    } else if (i < 4194304) {
        size_t o = i - 2097152;
        float2 v = ((const float2*)qw)[o];
        ((__half2*)h_qw)[o] = __floats2half2_rn(v.x, v.y);
    } else if (i < 4456448) {
        size_t o = i - 4194304;
        float2 v = ((const float2*)krw)[o];
        ((__half2*)h_krw)[o] = __floats2half2_rn(v.x, v.y);
    } else if (i < 4718592) {
        size_t o = i - 4456448;          // float2 index into dw [256][2048]
        size_t e = o * 2;
        int k = (int)(e >> 11), n = (int)(e & 2047);
        float2 v = ((const float2*)dw)[o];
        h_dwT[(size_t)n * 256 + k]       = __float2half_rn(v.x);
        h_dwT[(size_t)(n + 1) * 256 + k] = __float2half_rn(v.y);
    } else if (i < 4751360) {
        size_t o = i - 4718592;
        float2 v = ((const float2*)uk)[o];
        ((__half2*)h_ukuv)[o] = __floats2half2_rn(v.x, v.y);
    } else if (i < 4816896) {
        size_t o = i - 4751360;
        float2 v = ((const float2*)uv)[o];
        ((__half2*)h_ukuv)[32768 + o] = __floats2half2_rn(v.x, v.y);
    } else if (i < 6914048) {
        size_t o = i - 4816896;
        float2 v = ((const float2*)ow)[o];
        ((__half2*)h_ow)[o] = __floats2half2_rn(v.x, v.y);
    }
}

// ================= generic fp16 GEMM (ldmatrix): C[M,N] = A[M,K]*B[N,K]^T =================
// Block 128x128, K-tile 32, double-buffered cp.async, 8 warps = 4(m) x 2(n).
template<typename OutT>
__global__ __launch_bounds__(256) void gemm_h2(const __half* __restrict__ A,
                                               const __half* __restrict__ B,
                                               OutT* __restrict__ C,
                                               int M, int N, int K) {
    __shared__ __align__(16) __half As[2][128 * 40];
    __shared__ __align__(16) __half Bs[2][128 * 40];

    const int tid  = threadIdx.x;
    const int warp = tid >> 5, lane = tid & 31;
    const int grp  = lane >> 2, tig = lane & 3;
    const int m0   = blockIdx.y * 128, n0 = blockIdx.x * 128;
    const int wm   = (warp & 3) * 32, wn = (warp >> 2) * 64;

    const int aoff = ((lane >> 3) & 1) * 8 + (lane & 7);
    const int asel = (lane >> 4) * 8;
    const int boff = ((lane >> 4) & 1) * 8 + (lane & 7);
    const int bsel = ((lane >> 3) & 1) * 8;

    float c[2][8][4] = {};
    const int T = K >> 5;

    auto issue = [&](int t, int buf) {
        const __half* Ag = A + (size_t)m0 * K + t * 32;
        const __half* Bg = B + (size_t)n0 * K + t * 32;
        #pragma unroll
        for (int q = 0; q < 2; q++) {
            int ch = tid + q * 256;
            int r = ch >> 2, sg = ch & 3;
            cpa16(Ag + (size_t)r * K + sg * 8, &As[buf][r * 40 + sg * 8]);
            cpa16(Bg + (size_t)r * K + sg * 8, &Bs[buf][r * 40 + sg * 8]);
        }
    };

    issue(0, 0); CP_COMMIT;

    for (int t = 0; t < T; t++) {
        CP_WAIT0;
        __syncthreads();
        if (t + 1 < T) { issue(t + 1, (t + 1) & 1); CP_COMMIT; }
        const __half* as = As[t & 1];
        const __half* bs = Bs[t & 1];
        #pragma unroll
        for (int ks = 0; ks < 2; ks++) {
            const int kb = ks * 16;
            uint32_t a[2][4];
            ldsm4(a[0], &as[(wm + aoff) * 40 + kb + asel]);
            ldsm4(a[1], &as[(wm + 16 + aoff) * 40 + kb + asel]);
            #pragma unroll
            for (int np = 0; np < 4; np++) {
                uint32_t b[4];
                ldsm4(b, &bs[(wn + np * 16 + boff) * 40 + kb + bsel]);
                mma_f16(c[0][2 * np],     a[0][0], a[0][1], a[0][2], a[0][3], b[0], b[1]);
                mma_f16(c[1][2 * np],     a[1][0], a[1][1], a[1][2], a[1][3], b[0], b[1]);
                mma_f16(c[0][2 * np + 1], a[0][0], a[0][1], a[0][2], a[0][3], b[2], b[3]);
                mma_f16(c[1][2 * np + 1], a[1][0], a[1][1], a[1][2], a[1][3], b[2], b[3]);
            }
        }
    }

    #pragma unroll
    for (int mt = 0; mt < 2; mt++) {
        const int r_0 = m0 + wm + mt * 16 + grp;
        const int r_1 = r_0 + 8;
        #pragma unroll
        for (int nt = 0; nt < 8; nt++) {
            const int cc = n0 + wn + nt * 8 + 2 * tig;
            if constexpr (sizeof(OutT) == 4) {
                *(float2*)((float*)C + (size_t)r_0 * N + cc) =
                    make_float2(c[mt][nt][0], c[mt][nt][1]);
                *(float2*)((float*)C + (size_t)r_1 * N + cc) =
                    make_float2(c[mt][nt][2], c[mt][nt][3]);
            } else {
                *(__half2*)((__half*)C + (size_t)r_0 * N + cc) =
                    __floats2half2_rn(c[mt][nt][0], c[mt][nt][1]);
                *(__half2*)((__half*)C + (size_t)r_1 * N + cc) =
                    __floats2half2_rn(c[mt][nt][2], c[mt][nt][3]);
            }
        }
    }
}

// ================= fused input GEMM: [q | kr | kc | v] = hs @ Bconcat^T =================
// M=2048, N=3072, K=2048. B rows: [0,2048) q_w, [2048,2304) kr_w, [2304,3072) wcomb.
// Epilogue scatters by region; v region written transposed into g_vT.
__global__ __launch_bounds__(256) void gemm_big() {
    __shared__ __align__(16) __half As[2][128 * 40];
    __shared__ __align__(16) __half Bs[2][128 * 40];

    const int tid  = threadIdx.x;
    const int warp = tid >> 5, lane = tid & 31;
    const int grp  = lane >> 2, tig = lane & 3;
    const int m0   = blockIdx.y * 128, n0 = blockIdx.x * 128;
    const int wm   = (warp & 3) * 32, wn = (warp >> 2) * 64;

    const int aoff = ((lane >> 3) & 1) * 8 + (lane & 7);
    const int asel = (lane >> 4) * 8;
    const int boff = ((lane >> 4) & 1) * 8 + (lane & 7);
    const int bsel = ((lane >> 3) & 1) * 8;

    const __half* Bbase;
    if      (n0 < 2048) Bbase = h_qw   + (size_t)n0 * 2048;
    else if (n0 < 2304) Bbase = h_krw  + (size_t)(n0 - 2048) * 2048;
    else                Bbase = h_wcomb + (size_t)(n0 - 2304) * 2048;

    float c[2][8][4] = {};

    auto issue = [&](int t, int buf) {
        const __half* Ag = h_hs + (size_t)m0 * 2048 + t * 32;
        const __half* Bg = Bbase + t * 32;
        #pragma unroll
        for (int q = 0; q < 2; q++) {
            int ch = tid + q * 256;
            int r = ch >> 2, sg = ch & 3;
            cpa16(Ag + (size_t)r * 2048 + sg * 8, &As[buf][r * 40 + sg * 8]);
            cpa16(Bg + (size_t)r * 2048 + sg * 8, &Bs[buf][r * 40 + sg * 8]);
        }
    };

    issue(0, 0); CP_COMMIT;

    for (int t = 0; t < 64; t++) {
        CP_WAIT0;
        __syncthreads();
        if (t + 1 < 64) { issue(t + 1, (t + 1) & 1); CP_COMMIT; }
        const __half* as = As[t & 1];
        const __half* bs = Bs[t & 1];
        #pragma unroll
        for (int ks = 0; ks < 2; ks++) {
            const int kb = ks * 16;
            uint32_t a[2][4];
            ldsm4(a[0], &as[(wm + aoff) * 40 + kb + asel]);
            ldsm4(a[1], &as[(wm + 16 + aoff) * 40 + kb + asel]);
            #pragma unroll
            for (int np = 0; np < 4; np++) {
                uint32_t b[4];
                ldsm4(b, &bs[(wn + np * 16 + boff) * 40 + kb + bsel]);
                mma_f16(c[0][2 * np],     a[0][0], a[0][1], a[0][2], a[0][3], b[0], b[1]);
                mma_f16(c[1][2 * np],     a[1][0], a[1][1], a[1][2], a[1][3], b[0], b[1]);
                mma_f16(c[0][2 * np + 1], a[0][0], a[0][1], a[0][2], a[0][3], b[2], b[3]);
                mma_f16(c[1][2 * np + 1], a[1][0], a[1][1], a[1][2], a[1][3], b[2], b[3]);
            }
        }
    }

    #pragma unroll
    for (int mt = 0; mt < 2; mt++) {
        const int r_0 = m0 + wm + mt * 16 + grp;
        const int r_1 = r_0 + 8;
        #pragma unroll
        for (int nt = 0; nt < 8; nt++) {
            const int cc = n0 + wn + nt * 8 + 2 * tig;
            __half2 v0 = __floats2half2_rn(c[mt][nt][0], c[mt][nt][1]);
            __half2 v1 = __floats2half2_rn(c[mt][nt][2], c[mt][nt][3]);
            if (n0 < 2048) {
                *(__half2*)&g_q[(size_t)r_0 * 2048 + cc] = v0;
                *(__half2*)&g_q[(size_t)r_1 * 2048 + cc] = v1;
            } else if (n0 < 2304) {
                *(__half2*)&g_kr[(size_t)r_0 * 256 + cc - 2048] = v0;
                *(__half2*)&g_kr[(size_t)r_1 * 256 + cc - 2048] = v1;
            } else if (n0 < 2560) {
                *(__half2*)&g_kc[(size_t)r_0 * 256 + cc - 2304] = v0;
                *(__half2*)&g_kc[(size_t)r_1 * 256 + cc - 2304] = v1;
            } else {
                const int vd = cc - 2560;
                g_vT[(size_t)vd * 2048 + r_0]       = __low2half(v0);
                g_vT[(size_t)(vd + 1) * 2048 + r_0] = __high2half(v0);
                g_vT[(size_t)vd * 2048 + r_1]       = __low2half(v1);
                g_vT[(size_t)(vd + 1) * 2048 + r_1] = __high2half(v1);
            }
        }
    }
}

// ================= RoPE on q (in place, fold softmax scale 0.125) =================
__global__ void rope_q_kernel() {
    const int s = blockIdx.x;
    const int t = threadIdx.x;
    const int h = t >> 5;
    const int j = t & 31;
    float inv = powf(10000.0f, -(float)j * (1.0f / 32.0f));
    float sn, cs;
    sincosf((float)s * inv, &sn, &cs);
    __half* q = g_q + (size_t)s * HID + h * HD;
    float x = __half2float(q[j]);
    float y = __half2float(q[j + 32]);
    q[j]      = __float2half_rn(0.125f * (x * cs - y * sn));
    q[j + 32] = __float2half_rn(0.125f * (y * cs + x * sn));
}

// ================= assemble full key =================
__global__ void make_kf_kernel() {
    const int s = blockIdx.x;
    const int t = threadIdx.x;   // 512
    const int g = t >> 6;
    const int d = t & 63;
    const int j = d & 31;
    float out;
    if (j < 16) {
        const int selfc = g * 32 + ((d < 32) ? j : 16 + j);
        const int partc = g * 32 + ((d < 32) ? 16 + j : j);
        float inv = powf(10000.0f, -(float)j * (1.0f / 32.0f));
        float sn, cs;
        sincosf((float)s * inv, &sn, &cs);
        float x = __half2float(g_kr[(size_t)s * 256 + selfc]);
        float y = __half2float(g_kr[(size_t)s * 256 + partc]);
        out = (d < 32) ? (x * cs - y * sn) : (x * cs + y * sn);
    } else {
        const int cc = g * 32 + ((d < 32) ? (d - 16) : (d - 32));
        out = __half2float(g_kc[(size_t)s * 256 + cc]);
    }
    g_kf[(size_t)s * 512 + g * HD + d] = __float2half_rn(out);
}

// ================= fp16 flash attention (Q in regs, ldmatrix K/V) =================
// smem halves: Qs[128*72] @0 | Ks[2][64*72] @9216 | Vs[2][64*72] @18432
#define FA_SMEM_BYTES 55296

__global__ __launch_bounds__(256) void flash_h() {
    extern __shared__ __align__(16) __half smh[];
    __half* Qs  = smh;
    __half* Ks0 = smh + 9216;
    __half* Ks1 = Ks0 + 4608;
    __half* Vs0 = smh + 18432;
    __half* Vs1 = Vs0 + 4608;

    const int h = blockIdx.y;
    const int i = 15 - (int)blockIdx.x;   // heavy tiles first
    const int g = h >> 2;

    const int tid  = threadIdx.x;
    const int warp = tid >> 5, lane = tid & 31;
    const int grp  = lane >> 2, tig = lane & 3;
    const int wrow = warp * 16;

    const int aoff = ((lane >> 3) & 1) * 8 + (lane & 7);
    const int asel = (lane >> 4) * 8;
    const int boff = ((lane >> 4) & 1) * 8 + (lane & 7);
    const int bsel = ((lane >> 3) & 1) * 8;

    auto issueKV = [&](int j, int buf) {
        __half* kd = buf ? Ks1 : Ks0;
        __half* vd = buf ? Vs1 : Vs0;
        const __half* kg = g_kf + (size_t)(j * 64) * 512 + g * 64;
        const __half* vg = g_vT + (size_t)(g * 64) * 2048 + j * 64;
        #pragma unroll
        for (int q = 0; q < 2; q++) {
            int ch = tid + q * 256;
            int r = ch >> 3, sg = ch & 7;
            cpa16(kg + (size_t)r * 512 + sg * 8,  &kd[r * 72 + sg * 8]);
            cpa16(vg + (size_t)r * 2048 + sg * 8, &vd[r * 72 + sg * 8]);
        }
    };

    // prologue: Q tile + first K/V tile in one group
    {
        const __half* qg = g_q + (size_t)(i * 128) * 2048 + h * 64;
        for (int ch = tid; ch < 1024; ch += 256) {
            int r = ch >> 3, sg = ch & 7;
            cpa16(qg + (size_t)r * 2048 + sg * 8, &Qs[r * 72 + sg * 8]);
        }
        issueKV(0, 0);
        CP_COMMIT;
    }
    CP_WAIT0;
    __syncthreads();

    // hoist Q fragments to registers (reused across all tiles)
    uint32_t qf[4][4];
    #pragma unroll
    for (int kst = 0; kst < 4; kst++)
        ldsm4(qf[kst], &Qs[(wrow + aoff) * 72 + kst * 16 + asel]);

    float o[8][4] = {};
    float m_lo = -1e30f, m_hi = -1e30f, l_lo = 0.0f, l_hi = 0.0f;
    const int row_lo = i * 128 + wrow + grp;
    const int row_hi = row_lo + 8;

    const int ntiles = 2 * i + 2;
    for (int j = 0; j < ntiles; j++) {
        if (j + 1 < ntiles) { issueKV(j + 1, (j + 1) & 1); CP_COMMIT; }
        const __half* ks = (j & 1) ? Ks1 : Ks0;
        const __half* vs = (j & 1) ? Vs1 : Vs0;

        // ---- S = Q K^T ----
        float s[8][4] = {};
        #pragma unroll
        for (int kst = 0; kst < 4; kst++) {
            const int kb = kst * 16;
            #pragma unroll
            for (int np = 0; np < 4; np++) {
                uint32_t b[4];
                ldsm4(b, &ks[(np * 16 + boff) * 72 + kb + bsel]);
                mma_f16(s[2 * np],     qf[kst][0], qf[kst][1], qf[kst][2], qf[kst][3], b[0], b[1]);
                mma_f16(s[2 * np + 1], qf[kst][0], qf[kst][1], qf[kst][2], qf[kst][3], b[2], b[3]);
            }
        }

        // ---- causal mask ----
        if (j * 64 + 63 > row_lo) {
            #pragma unroll
            for (int nt = 0; nt < 8; nt++) {
                const int col0 = j * 64 + nt * 8 + 2 * tig;
                if (col0     > row_lo) s[nt][0] = -1e30f;
                if (col0 + 1 > row_lo) s[nt][1] = -1e30f;
                if (col0     > row_hi) s[nt][2] = -1e30f;
                if (col0 + 1 > row_hi) s[nt][3] = -1e30f;
            }
        }

        // ---- online softmax (warp-local), pack P into A-fragments ----
        float tlo = -1e30f, thi = -1e30f;
        #pragma unroll
        for (int nt = 0; nt < 8; nt++) {
            tlo = fmaxf(tlo, fmaxf(s[nt][0], s[nt][1]));
            thi = fmaxf(thi, fmaxf(s[nt][2], s[nt][3]));
        }
        tlo = fmaxf(tlo, __shfl_xor_sync(0xffffffff, tlo, 1));
        tlo = fmaxf(tlo, __shfl_xor_sync(0xffffffff, tlo, 2));
        thi = fmaxf(thi, __shfl_xor_sync(0xffffffff, thi, 1));
        thi = fmaxf(thi, __shfl_xor_sync(0xffffffff, thi, 2));

        const float mnl = fmaxf(m_lo, tlo);
        const float mnh = fmaxf(m_hi, thi);
        const float alo = __expf(m_lo - mnl);
        const float ahi = __expf(m_hi - mnh);

        uint32_t ph[8][2];
        float slo = 0.0f, shi = 0.0f;
        #pragma unroll
        for (int nt = 0; nt < 8; nt++) {
            const float p0 = __expf(s[nt][0] - mnl);
            const float p1 = __expf(s[nt][1] - mnl);
            const float p2 = __expf(s[nt][2] - mnh);
            const float p3 = __expf(s[nt][3] - mnh);
            slo += p0 + p1;
            shi += p2 + p3;
            ph[nt][0] = packh2(p0, p1);
            ph[nt][1] = packh2(p2, p3);
        }
        slo += __shfl_xor_sync(0xffffffff, slo, 1);
        slo += __shfl_xor_sync(0xffffffff, slo, 2);
        shi += __shfl_xor_sync(0xffffffff, shi, 1);
        shi += __shfl_xor_sync(0xffffffff, shi, 2);

        l_lo = l_lo * alo + slo;
        l_hi = l_hi * ahi + shi;
        m_lo = mnl; m_hi = mnh;

        #pragma unroll
        for (int nt = 0; nt < 8; nt++) {
            o[nt][0] *= alo; o[nt][1] *= alo;
            o[nt][2] *= ahi; o[nt][3] *= ahi;
        }

        // ---- O += P V ----
        #pragma unroll
        for (int j2 = 0; j2 < 4; j2++) {
            const int kb = j2 * 16;
            uint32_t a0 = ph[2 * j2][0],     a1 = ph[2 * j2][1];
            uint32_t a2 = ph[2 * j2 + 1][0], a3 = ph[2 * j2 + 1][1];
            #pragma unroll
            for (int np = 0; np < 4; np++) {
                uint32_t b[4];
                ldsm4(b, &vs[(np * 16 + boff) * 72 + kb + bsel]);
                mma_f16(o[2 * np],     a0, a1, a2, a3, b[0], b[1]);
                mma_f16(o[2 * np + 1], a0, a1, a2, a3, b[2], b[3]);
            }
        }

        if (j + 1 < ntiles) { CP_WAIT0; __syncthreads(); }
    }

    // ---- epilogue ----
    const float inv_lo = 1.0f / l_lo;
    const float inv_hi = 1.0f / l_hi;
    #pragma unroll
    for (int nt = 0; nt < 8; nt++) {
        const int col = h * HD + nt * 8 + 2 * tig;
        *(__half2*)&g_attn[(size_t)row_lo * HID + col] =
            __floats2half2_rn(o[nt][0] * inv_lo, o[nt][1] * inv_lo);
        *(__half2*)&g_attn[(size_t)row_hi * HID + col] =
            __floats2half2_rn(o[nt][2] * inv_hi, o[nt][3] * inv_hi);
    }
}

// ================= launch =================
extern "C" void kernel_launch(void* const* d_in, const int* in_sizes, int n_in,
                              void* d_out, int out_size) {
    const float* hs     = (const float*)d_in[0];
    const float* q_w    = (const float*)d_in[1];
    const float* kr_w   = (const float*)d_in[2];
    const float* down_w = (const float*)d_in[3];
    const float* upk_w  = (const float*)d_in[4];
    const float* upv_w  = (const float*)d_in[5];
    const float* o_w    = (const float*)d_in[6];
    float* out = (float*)d_out;

    __half *p_ukuv, *p_dwT, *p_wcomb, *p_attn, *p_ow;
    cudaGetSymbolAddress((void**)&p_ukuv, h_ukuv);
    cudaGetSymbolAddress((void**)&p_dwT,  h_dwT);
    cudaGetSymbolAddress((void**)&p_wcomb, h_wcomb);
    cudaGetSymbolAddress((void**)&p_attn, g_attn);
    cudaGetSymbolAddress((void**)&p_ow,   h_ow);

    cudaFuncSetAttribute(flash_h, cudaFuncAttributeMaxDynamicSharedMemorySize,
                         FA_SMEM_BYTES);

    // convert / reshuffle all inputs to fp16
    cvt_all<<<27008, 256>>>(hs, q_w, kr_w, down_w, upk_w, upv_w, o_w);

    // W_comb[768,2048] = [upk;upv] @ down_w
    gemm_h2<__half><<<dim3(16, 6), 256>>>(p_ukuv, p_dwT, p_wcomb, 768, 2048, 256);

    // fused input projections: q | kr | kc | v (v transposed)
    gemm_big<<<dim3(24, 16), 256>>>();

    // rope + key assembly
    rope_q_kernel<<<S_LEN, 1024>>>();
    make_kf_kernel<<<S_LEN, 512>>>();

    // attention
    flash_h<<<dim3(16, NH), 256, FA_SMEM_BYTES>>>();

    // output projection (fp32 out)
    gemm_h2<float><<<dim3(16, 16), 256>>>(p_attn, p_ow, out, S_LEN, HID, NH * HD);
}